// round 16
// baseline (speedup 1.0000x reference)
#include <cuda_runtime.h>
#include <cuda_fp16.h>
#include <cstdint>

#define BATCH 8
#define NPTS  2048
#define CIN   64
#define NIP   256            // H width: [c(64) | e(192)]
#define MT    64             // a-rows per CTA == b-tile size
#define KC    64             // b's per chunk
#define NCHUNK (NPTS / KC)   // 32
#define THREADS 256
#define NCTAS  (BATCH * NCHUNK)   // 256 total CTAs (all co-resident at 2/SM)

// Static device scratch (allocation is forbidden)
__device__ __align__(128) __half g_H[(size_t)BATCH * NIP * NPTS];  // [z][i'][b] fp16
__device__ int g_bar;   // device-wide barrier counter (memset to 0 per launch)

// ---- smem layout (bytes) ----
#define GEOM_OFF 0u                  // 2048 x float4 = 32768
#define A_OFF    32768u              // 2 x 8192 (64 rows x 128B, SW128)
#define A_STG    8192u
#define B_OFF    49152u              // 2 x 32768 (256 rows x 128B, SW128)
#define B_STG    32768u
#define SMEM_MAIN (B_OFF + 2u * B_STG)   // 114688 -> 2 CTAs/SM
// phase A reuses bytes [B_OFF, B_OFF+48KB) as Wk scratch before the GEMM

__device__ __forceinline__ uint32_t smem_u32(const void* p) {
    uint32_t a;
    asm("{ .reg .u64 t; cvta.to.shared.u64 t, %1; cvt.u32.u64 %0, t; }" : "=r"(a) : "l"(p));
    return a;
}
__device__ __forceinline__ void cpasync16(uint32_t dst, const void* src) {
    asm volatile("cp.async.cg.shared.global [%0], [%1], 16;" :: "r"(dst), "l"(src) : "memory");
}
__device__ __forceinline__ void sts32(uint32_t a, uint32_t v) {
    asm volatile("st.shared.b32 [%0], %1;" :: "r"(a), "r"(v) : "memory");
}
__device__ __forceinline__ void ldsm_x4(uint32_t& r0, uint32_t& r1, uint32_t& r2, uint32_t& r3,
                                        uint32_t addr) {
    asm volatile("ldmatrix.sync.aligned.m8n8.x4.shared.b16 {%0,%1,%2,%3}, [%4];"
                 : "=r"(r0), "=r"(r1), "=r"(r2), "=r"(r3) : "r"(addr));
}
__device__ __forceinline__ void mma16816(float& d0, float& d1, float& d2, float& d3,
                                         uint32_t a0, uint32_t a1, uint32_t a2, uint32_t a3,
                                         uint32_t b0, uint32_t b1) {
    asm volatile(
        "mma.sync.aligned.m16n8k16.row.col.f32.f16.f16.f32 "
        "{%0,%1,%2,%3}, {%4,%5,%6,%7}, {%8,%9}, {%0,%1,%2,%3};"
        : "+f"(d0), "+f"(d1), "+f"(d2), "+f"(d3)
        : "r"(a0), "r"(a1), "r"(a2), "r"(a3), "r"(b0), "r"(b1));
}

// ---- packed f32x2 helpers (sm_100+ base ISA) ----
__device__ __forceinline__ void unpack2(float& lo, float& hi, uint64_t v) {
    asm("mov.b64 {%0, %1}, %2;" : "=f"(lo), "=f"(hi) : "l"(v));
}
__device__ __forceinline__ uint64_t fma2(uint64_t a, uint64_t b, uint64_t c) {
    uint64_t d;
    asm("fma.rn.f32x2 %0, %1, %2, %3;" : "=l"(d) : "l"(a), "l"(b), "l"(c));
    return d;
}

// issue one chunk's B copies (256 rows x 128B, SW128-swizzled)
__device__ __forceinline__ void issue_b_copies(uint32_t bst, int z, int b0, int t) {
#pragma unroll
    for (int it = 0; it < 8; it++) {
        const int m = t + THREADS * it;          // 0..2047
        const int row = m >> 3, c16 = m & 7;
        const uint32_t dst = bst + (uint32_t)row * 128u
                           + (uint32_t)((c16 ^ (row & 7)) << 4);
        const __half* src = g_H + (((size_t)z * NIP + row) * NPTS + b0 + c16 * 8);
        cpasync16(dst, src);
    }
}

// ---------------------------------------------------------------------------
// Fused kernel.
// Phase A (b-paired): thread owns b-pair (a0+2lp, a0+2lp+1) and 8 H-row
//   indices; each Wk smem row load feeds both b's (LDS halved vs R15);
//   per-(i,b) FP chains identical to R15 -> bit-identical H.
// Device barrier: 256 CTAs co-resident (2/SM via launch_bounds).
// Phase B: verbatim R15 GEMM: P[64 x 256] = M @ H, fp16 HMMA, 8 warps,
//   warp tile 32x64, 1 sync/chunk, double-buffered B, in-CTA mask tile.
// ---------------------------------------------------------------------------
__global__ __launch_bounds__(THREADS, 2) void conv_fused_kernel(
    const float* __restrict__ feat,
    const float* __restrict__ geom,
    const float* __restrict__ Wk,
    float* __restrict__ out)
{
    extern __shared__ __align__(16) char smem[];
    const uint32_t su = smem_u32(smem);
    float4* g4 = reinterpret_cast<float4*>(smem);

    const int z  = blockIdx.y;
    const int a0 = blockIdx.x * MT;      // also this CTA's b-tile base
    const int t  = threadIdx.x;
    const int wid = t >> 5, lane = t & 31;
    const int m0 = (wid >> 2) * 32, n0 = (wid & 3) * 64;

    const float* gz = geom + (size_t)z * NPTS * 3;

    // ---- stage whole-z geometry as float4 (phase A c-rows + maskgen) ----
    {
        float* gf = reinterpret_cast<float*>(smem);
        for (int idx = t; idx < NPTS * 3; idx += THREADS)
            gf[(idx / 3) * 4 + (idx % 3)] = gz[idx];
    }

    // ---- phase A: produce H[z][*][a0..a0+63], two b's per thread ----
    {
        float* s_wk = reinterpret_cast<float*>(smem + B_OFF);   // 48KB scratch
        for (int m = t; m < 3 * 64 * 64 / 4; m += 256)
            reinterpret_cast<float4*>(s_wk)[m] = reinterpret_cast<const float4*>(Wk)[m];

        const int q = t >> 5, lp = t & 31;       // q: 8 i-groups of 8
        const int bg0 = a0 + 2 * lp;             // even b; pair is (bg0, bg0+1)
        ulonglong2 f0[16], f1[16];               // feature rows, packed f32x2
        {
            const ulonglong2* fp0 = reinterpret_cast<const ulonglong2*>(
                feat + ((size_t)z * NPTS + bg0) * CIN);
            const ulonglong2* fp1 = reinterpret_cast<const ulonglong2*>(
                feat + ((size_t)z * NPTS + bg0 + 1) * CIN);
#pragma unroll
            for (int c = 0; c < 16; c++) { f0[c] = fp0[c]; f1[c] = fp1[c]; }
        }
        __syncthreads();   // wk + geometry staged

        const float4 gbA = g4[bg0];
        const float4 gbB = g4[bg0 + 1];
        uint32_t* Hw = reinterpret_cast<uint32_t*>(g_H);
        const size_t hb = ((size_t)(bg0) >> 1);  // u32 column index

#pragma unroll 1
        for (int n = 0; n < 8; n++) {
            const int i = q * 8 + n;
            float E0x, E0y, E0z, E1x, E1y, E1z;
#pragma unroll
            for (int x = 0; x < 3; x++) {
                const ulonglong2* w = reinterpret_cast<const ulonglong2*>(
                    s_wk + (x * 64 + i) * 64);
                uint64_t a01_0 = 0ull, a23_0 = 0ull, a01_1 = 0ull, a23_1 = 0ull;
#pragma unroll
                for (int c = 0; c < 16; c++) {
                    const ulonglong2 wv = w[c];
                    a01_0 = fma2(f0[c].x, wv.x, a01_0);
                    a23_0 = fma2(f0[c].y, wv.y, a23_0);
                    a01_1 = fma2(f1[c].x, wv.x, a01_1);
                    a23_1 = fma2(f1[c].y, wv.y, a23_1);
                }
                float e0, e1, e2, e3, g0, g1, g2, g3;
                unpack2(e0, e1, a01_0); unpack2(e2, e3, a23_0);
                unpack2(g0, g1, a01_1); unpack2(g2, g3, a23_1);
                const float E0 = (e0 + e1) + (e2 + e3);
                const float E1 = (g0 + g1) + (g2 + g3);
                if (x == 0) { E0x = E0; E1x = E1; }
                else if (x == 1) { E0y = E0; E1y = E1; }
                else { E0z = E0; E1z = E1; }
                const __half2 h = __halves2half2(__float2half_rn(E0),
                                                 __float2half_rn(E1));
                Hw[((size_t)z * NIP + 64 + 64 * x + i) * (NPTS / 2) + hb] =
                    *reinterpret_cast<const uint32_t*>(&h);
            }
            const float c0 = fmaf(gbA.x, E0x, fmaf(gbA.y, E0y, gbA.z * E0z));
            const float c1 = fmaf(gbB.x, E1x, fmaf(gbB.y, E1y, gbB.z * E1z));
            const __half2 hc = __halves2half2(__float2half_rn(c0),
                                              __float2half_rn(c1));
            Hw[((size_t)z * NIP + i) * (NPTS / 2) + hb] =
                *reinterpret_cast<const uint32_t*>(&hc);
        }
    }

    // ---- device-wide barrier (all 256 CTAs co-resident) ----
    __threadfence();          // make this thread's H stores device-visible
    __syncthreads();
    if (t == 0) {
        atomicAdd(&g_bar, 1);
        while (*reinterpret_cast<volatile int*>(&g_bar) < NCTAS) {}
        __threadfence();
    }
    __syncthreads();

    // ---- phase B prologue: chunk-0 B copies ----
    issue_b_copies(su + B_OFF, z, 0, t);
    asm volatile("cp.async.commit_group;" ::: "memory");

    // maskgen consts: thread t -> row rg (0..63), k-quarter sg
    const int rg = t >> 2, sg = t & 3;
    const float4 ga = g4[a0 + rg];
    const uint32_t aw_base = su + A_OFF + (uint32_t)rg * 128u;
    const uint32_t rx = (uint32_t)(rg & 7);

    // ldsm lane bases
    const int rowA = m0 + ((lane >> 3) & 1) * 8 + (lane & 7);
    const uint32_t sA = (uint32_t)(lane >> 4), rxA = (uint32_t)(rowA & 7);
    const int rowB = n0 + ((lane >> 4) & 1) * 8 + (lane & 7);
    const uint32_t sB = (uint32_t)((lane >> 3) & 1), rxB = (uint32_t)(rowB & 7);

    float d[2][8][4];
#pragma unroll
    for (int mt = 0; mt < 2; mt++)
#pragma unroll
        for (int nt = 0; nt < 8; nt++)
#pragma unroll
            for (int r = 0; r < 4; r++) d[mt][nt][r] = 0.0f;

#pragma unroll 1
    for (int i = 0; i < NCHUNK; i++) {
        const uint32_t p = (uint32_t)(i & 1);
        const int b0 = i * KC;

        // ---- mask tile A[64 x 64] fp16 (SW128), diff-form norm test ----
        {
            const uint32_t ast = aw_base + p * A_STG;
#pragma unroll
            for (int v = 0; v < 8; v++) {
                const int veff = (v + sg) & 7;
                const int k0 = sg * 16 + 2 * veff;
                const float4 q0 = g4[b0 + k0];
                const float4 q1 = g4[b0 + k0 + 1];
                const float dx0 = q0.x - ga.x, dy0 = q0.y - ga.y, dz0 = q0.z - ga.z;
                const float dx1 = q1.x - ga.x, dy1 = q1.y - ga.y, dz1 = q1.z - ga.z;
                const float nn0 = fmaf(dx0, dx0, fmaf(dy0, dy0, dz0 * dz0));
                const float nn1 = fmaf(dx1, dx1, fmaf(dy1, dy1, dz1 * dz1));
                const uint32_t val = (nn0 < 1.0f ? 0x3C00u : 0u)
                                   | (nn1 < 1.0f ? 0x3C000000u : 0u);
                const uint32_t bc = (uint32_t)(2 * k0);
                sts32(ast + (((bc >> 4) ^ rx) << 4) + (bc & 15u), val);
            }
        }

        asm volatile("cp.async.wait_group 0;" ::: "memory");   // B(j) complete
        __syncthreads();   // A(p)+B(p) visible; all warps done with stage p^1

        if (i + 1 < NCHUNK) {
            issue_b_copies(su + B_OFF + (p ^ 1u) * B_STG, z, b0 + KC, t);
            asm volatile("cp.async.commit_group;" ::: "memory");
        }

        // ---- ldmatrix + 64 HMMA per warp ----
        {
            const uint32_t Ast = su + A_OFF + p * A_STG;
            const uint32_t Bst = su + B_OFF + p * B_STG;
#pragma unroll
            for (int kk = 0; kk < 4; kk++) {
                uint32_t af[2][4];
#pragma unroll
                for (int mt = 0; mt < 2; mt++)
                    ldsm_x4(af[mt][0], af[mt][1], af[mt][2], af[mt][3],
                            Ast + (uint32_t)(rowA + mt * 16) * 128u
                                + ((((uint32_t)kk * 2u + sA) ^ rxA) << 4));
#pragma unroll
                for (int ntp = 0; ntp < 4; ntp++) {
                    uint32_t b0r, b1r, b2r, b3r;
                    ldsm_x4(b0r, b1r, b2r, b3r,
                            Bst + (uint32_t)(rowB + ntp * 16) * 128u
                               + ((((uint32_t)kk * 2u + sB) ^ rxB) << 4));
#pragma unroll
                    for (int mt = 0; mt < 2; mt++) {
                        mma16816(d[mt][2*ntp][0], d[mt][2*ntp][1], d[mt][2*ntp][2], d[mt][2*ntp][3],
                                 af[mt][0], af[mt][1], af[mt][2], af[mt][3], b0r, b1r);
                        mma16816(d[mt][2*ntp+1][0], d[mt][2*ntp+1][1], d[mt][2*ntp+1][2], d[mt][2*ntp+1][3],
                                 af[mt][0], af[mt][1], af[mt][2], af[mt][3], b2r, b3r);
                    }
                }
            }
        }
    }

    // ---- epilogue: P (overlays A/B region), combine, store ----
    __syncthreads();
    float* P = reinterpret_cast<float*>(smem + A_OFF);   // [64][260]
    const int fr = lane >> 2, fc = lane & 3;
#pragma unroll
    for (int mt = 0; mt < 2; mt++) {
#pragma unroll
        for (int nt = 0; nt < 8; nt++) {
            const int R0 = m0 + mt * 16 + fr;
            const int C  = n0 + nt * 8 + 2 * fc;
            *reinterpret_cast<float2*>(P + R0 * 260 + C)       = make_float2(d[mt][nt][0], d[mt][nt][1]);
            *reinterpret_cast<float2*>(P + (R0 + 8) * 260 + C) = make_float2(d[mt][nt][2], d[mt][nt][3]);
        }
    }
    __syncthreads();

    {
        const int al = t >> 2, iq = t & 3;
        const float4 ga4 = g4[a0 + al];
        float* orow = out + ((size_t)z * NPTS + a0 + al) * 64;
        const float* Pr = P + al * 260;
#pragma unroll
        for (int u = 0; u < 4; u++) {
            const int i0 = iq * 16 + u * 4;
            const float4 vc = *reinterpret_cast<const float4*>(Pr + i0);
            const float4 v1 = *reinterpret_cast<const float4*>(Pr + 64 + i0);
            const float4 v2 = *reinterpret_cast<const float4*>(Pr + 128 + i0);
            const float4 v3 = *reinterpret_cast<const float4*>(Pr + 192 + i0);
            float4 o;
            o.x = fmaf(-ga4.z, v3.x, fmaf(-ga4.y, v2.x, fmaf(-ga4.x, v1.x, vc.x)));
            o.y = fmaf(-ga4.z, v3.y, fmaf(-ga4.y, v2.y, fmaf(-ga4.x, v1.y, vc.y)));
            o.z = fmaf(-ga4.z, v3.z, fmaf(-ga4.y, v2.z, fmaf(-ga4.x, v1.z, vc.z)));
            o.w = fmaf(-ga4.z, v3.w, fmaf(-ga4.y, v2.w, fmaf(-ga4.x, v1.w, vc.w)));
            *reinterpret_cast<float4*>(orow + i0) = o;
        }
    }
}

// ---------------------------------------------------------------------------
// Launcher. Inputs: features [8,2048,64] f32, geometry [8,2048,3] f32,
// Wk [3,64,64] f32. Output [8,2048,64] f32.
// Single compute launch; g_bar zeroed via graph-capturable memset.
// ---------------------------------------------------------------------------
extern "C" void kernel_launch(void* const* d_in, const int* in_sizes, int n_in,
                              void* d_out, int out_size) {
    const float* feat = (const float*)d_in[0];
    const float* geom = (const float*)d_in[1];
    const float* Wk   = (const float*)d_in[2];
    float* out = (float*)d_out;
    (void)in_sizes; (void)n_in; (void)out_size;

    void* bar_ptr = nullptr;
    cudaGetSymbolAddress(&bar_ptr, g_bar);
    cudaMemsetAsync(bar_ptr, 0, sizeof(int), 0);

    cudaFuncSetAttribute(conv_fused_kernel,
                         cudaFuncAttributeMaxDynamicSharedMemorySize, SMEM_MAIN);
    conv_fused_kernel<<<dim3(NPTS / MT, BATCH), THREADS, SMEM_MAIN>>>(
        feat, geom, Wk, out);
}

// round 17
// speedup vs baseline: 1.3291x; 1.3291x over previous
#include <cuda_runtime.h>
#include <cuda_fp16.h>
#include <cstdint>

#define BATCH 8
#define NPTS  2048
#define CIN   64
#define NIP   256            // H width: [c(64) | e(192)]
#define MT    128            // a-rows per CTA == b-tile size
#define KC    64             // b's per chunk
#define NCHUNK (NPTS / KC)   // 32
#define THREADS 512
#define NCTAS  (BATCH * NPTS / MT)   // 128 CTAs (1/SM, all co-resident)

// Static device scratch (allocation is forbidden)
__device__ __align__(128) __half g_H[(size_t)BATCH * NIP * NPTS];  // [z][i'][b] fp16
__device__ int g_bar;   // device-wide barrier counter (memset to 0 per launch)

// ---- smem layout (bytes) ----
#define GEOM_OFF 0u                  // 2048 x float4 = 32768
#define A_OFF    32768u              // 2 x 16384 (128 rows x 128B, SW128)
#define A_STG    16384u
#define B_OFF    65536u              // 2 x 32768 (256 rows x 128B, SW128)
#define B_STG    32768u
#define SMEM_MAIN (B_OFF + 2u * B_STG)   // 131072 -> 1 CTA/SM
// phase A reuses bytes [B_OFF, B_OFF+48KB) as Wk scratch before the GEMM

__device__ __forceinline__ uint32_t smem_u32(const void* p) {
    uint32_t a;
    asm("{ .reg .u64 t; cvta.to.shared.u64 t, %1; cvt.u32.u64 %0, t; }" : "=r"(a) : "l"(p));
    return a;
}
__device__ __forceinline__ void cpasync16(uint32_t dst, const void* src) {
    asm volatile("cp.async.cg.shared.global [%0], [%1], 16;" :: "r"(dst), "l"(src) : "memory");
}
__device__ __forceinline__ void sts32(uint32_t a, uint32_t v) {
    asm volatile("st.shared.b32 [%0], %1;" :: "r"(a), "r"(v) : "memory");
}
__device__ __forceinline__ void ldsm_x4(uint32_t& r0, uint32_t& r1, uint32_t& r2, uint32_t& r3,
                                        uint32_t addr) {
    asm volatile("ldmatrix.sync.aligned.m8n8.x4.shared.b16 {%0,%1,%2,%3}, [%4];"
                 : "=r"(r0), "=r"(r1), "=r"(r2), "=r"(r3) : "r"(addr));
}
__device__ __forceinline__ void mma16816(float& d0, float& d1, float& d2, float& d3,
                                         uint32_t a0, uint32_t a1, uint32_t a2, uint32_t a3,
                                         uint32_t b0, uint32_t b1) {
    asm volatile(
        "mma.sync.aligned.m16n8k16.row.col.f32.f16.f16.f32 "
        "{%0,%1,%2,%3}, {%4,%5,%6,%7}, {%8,%9}, {%0,%1,%2,%3};"
        : "+f"(d0), "+f"(d1), "+f"(d2), "+f"(d3)
        : "r"(a0), "r"(a1), "r"(a2), "r"(a3), "r"(b0), "r"(b1));
}

// ---- packed f32x2 helpers (sm_100+ base ISA) ----
__device__ __forceinline__ void unpack2(float& lo, float& hi, uint64_t v) {
    asm("mov.b64 {%0, %1}, %2;" : "=f"(lo), "=f"(hi) : "l"(v));
}
__device__ __forceinline__ uint64_t fma2(uint64_t a, uint64_t b, uint64_t c) {
    uint64_t d;
    asm("fma.rn.f32x2 %0, %1, %2, %3;" : "=l"(d) : "l"(a), "l"(b), "l"(c));
    return d;
}

// issue one chunk's B copies (256 rows x 128B, SW128-swizzled), 512 threads
__device__ __forceinline__ void issue_b_copies(uint32_t bst, int z, int b0, int t) {
#pragma unroll
    for (int it = 0; it < 4; it++) {
        const int m = t + THREADS * it;          // 0..2047
        const int row = m >> 3, c16 = m & 7;
        const uint32_t dst = bst + (uint32_t)row * 128u
                           + (uint32_t)((c16 ^ (row & 7)) << 4);
        const __half* src = g_H + (((size_t)z * NIP + row) * NPTS + b0 + c16 * 8);
        cpasync16(dst, src);
    }
}

// ---------------------------------------------------------------------------
// Fused kernel, R8 shape (512 threads / 16 warps / MT=128 / 1 CTA per SM).
// Phase A: this CTA produces H[z][*][b-tile] (R15's register-safe layout:
//   thread = (b-col, i-group of 16); FP chains bit-identical to R14/R15).
// Device barrier: 128 CTAs, all co-resident.
// Phase B: P[128 x 256] = M @ H, fp16 HMMA, warp tile 32x64 (4x4 warp grid),
//   1 syncthreads per chunk, double-buffered B, in-CTA mask tile.
// Epilogue: two-pass (64 rows each) through smem P[64][260].
// ---------------------------------------------------------------------------
__global__ __launch_bounds__(THREADS, 1) void conv_fused_kernel(
    const float* __restrict__ feat,
    const float* __restrict__ geom,
    const float* __restrict__ Wk,
    float* __restrict__ out)
{
    extern __shared__ __align__(16) char smem[];
    const uint32_t su = smem_u32(smem);
    float4* g4 = reinterpret_cast<float4*>(smem);

    const int z  = blockIdx.y;
    const int a0 = blockIdx.x * MT;      // also this CTA's b-tile base
    const int t  = threadIdx.x;
    const int wid = t >> 5, lane = t & 31;
    const int m0 = (wid >> 2) * 32, n0 = (wid & 3) * 64;

    const float* gz = geom + (size_t)z * NPTS * 3;

    // ---- stage whole-z geometry as float4 ----
    {
        float* gf = reinterpret_cast<float*>(smem);
        for (int idx = t; idx < NPTS * 3; idx += THREADS)
            gf[(idx / 3) * 4 + (idx % 3)] = gz[idx];
    }

    // ---- phase A: produce H[z][*][a0..a0+127] (R15 layout, 128 b-cols) ----
    {
        float* s_wk = reinterpret_cast<float*>(smem + B_OFF);   // 48KB scratch
        for (int m = t; m < 3 * 64 * 64 / 4; m += THREADS)
            reinterpret_cast<float4*>(s_wk)[m] = reinterpret_cast<const float4*>(Wk)[m];

        const int bl = t & 127, q = t >> 7;      // q: 4 i-groups of 16
        const int bg = a0 + bl;
        ulonglong2 fr[16];   // feature row, packed f32x2 pairs (32 regs)
        const ulonglong2* fp = reinterpret_cast<const ulonglong2*>(
            feat + ((size_t)z * NPTS + bg) * CIN);
#pragma unroll
        for (int c = 0; c < 16; c++) fr[c] = fp[c];
        __syncthreads();   // wk + geometry staged

        const float4 gb = g4[bg];
        __half* Hp = g_H;

#pragma unroll 1
        for (int n = 0; n < 16; n++) {
            const int i = q * 16 + n;
            float Ex0, Ex1, Ex2;
#pragma unroll
            for (int x = 0; x < 3; x++) {
                const ulonglong2* w = reinterpret_cast<const ulonglong2*>(
                    s_wk + (x * 64 + i) * 64);
                uint64_t acc01 = 0ull, acc23 = 0ull;
#pragma unroll
                for (int c = 0; c < 16; c++) {
                    acc01 = fma2(fr[c].x, w[c].x, acc01);
                    acc23 = fma2(fr[c].y, w[c].y, acc23);
                }
                float e0, e1, e2, e3;
                unpack2(e0, e1, acc01);
                unpack2(e2, e3, acc23);
                const float E = (e0 + e1) + (e2 + e3);
                if (x == 0) Ex0 = E; else if (x == 1) Ex1 = E; else Ex2 = E;
                Hp[((size_t)z * NIP + 64 + 64 * x + i) * NPTS + bg] = __float2half_rn(E);
            }
            const float cv = fmaf(gb.x, Ex0, fmaf(gb.y, Ex1, gb.z * Ex2));
            Hp[((size_t)z * NIP + i) * NPTS + bg] = __float2half_rn(cv);
        }
    }

    // ---- device-wide barrier (all 128 CTAs co-resident at 1/SM) ----
    __threadfence();
    __syncthreads();
    if (t == 0) {
        atomicAdd(&g_bar, 1);
        while (*reinterpret_cast<volatile int*>(&g_bar) < NCTAS) {}
        __threadfence();
    }
    __syncthreads();

    // ---- phase B prologue: chunk-0 B copies ----
    issue_b_copies(su + B_OFF, z, 0, t);
    asm volatile("cp.async.commit_group;" ::: "memory");

    // maskgen consts: thread t -> row rg (0..127), k-quarter sg
    const int rg = t >> 2, sg = t & 3;
    const float4 ga = g4[a0 + rg];
    const uint32_t aw_base = su + A_OFF + (uint32_t)rg * 128u;
    const uint32_t rx = (uint32_t)(rg & 7);

    // ldsm lane bases
    const int rowA = m0 + ((lane >> 3) & 1) * 8 + (lane & 7);
    const uint32_t sA = (uint32_t)(lane >> 4), rxA = (uint32_t)(rowA & 7);
    const int rowB = n0 + ((lane >> 4) & 1) * 8 + (lane & 7);
    const uint32_t sB = (uint32_t)((lane >> 3) & 1), rxB = (uint32_t)(rowB & 7);

    float d[2][8][4];
#pragma unroll
    for (int mt = 0; mt < 2; mt++)
#pragma unroll
        for (int nt = 0; nt < 8; nt++)
#pragma unroll
            for (int r = 0; r < 4; r++) d[mt][nt][r] = 0.0f;

#pragma unroll 1
    for (int i = 0; i < NCHUNK; i++) {
        const uint32_t p = (uint32_t)(i & 1);
        const int b0 = i * KC;

        // ---- mask tile A[128 x 64] fp16 (SW128), diff-form norm test ----
        {
            const uint32_t ast = aw_base + p * A_STG;
#pragma unroll
            for (int v = 0; v < 8; v++) {
                const int veff = (v + sg) & 7;
                const int k0 = sg * 16 + 2 * veff;
                const float4 q0 = g4[b0 + k0];
                const float4 q1 = g4[b0 + k0 + 1];
                const float dx0 = q0.x - ga.x, dy0 = q0.y - ga.y, dz0 = q0.z - ga.z;
                const float dx1 = q1.x - ga.x, dy1 = q1.y - ga.y, dz1 = q1.z - ga.z;
                const float nn0 = fmaf(dx0, dx0, fmaf(dy0, dy0, dz0 * dz0));
                const float nn1 = fmaf(dx1, dx1, fmaf(dy1, dy1, dz1 * dz1));
                const uint32_t val = (nn0 < 1.0f ? 0x3C00u : 0u)
                                   | (nn1 < 1.0f ? 0x3C000000u : 0u);
                const uint32_t bc = (uint32_t)(2 * k0);
                sts32(ast + (((bc >> 4) ^ rx) << 4) + (bc & 15u), val);
            }
        }

        asm volatile("cp.async.wait_group 0;" ::: "memory");   // B(j) complete
        __syncthreads();   // A(p)+B(p) visible; all warps done with stage p^1

        if (i + 1 < NCHUNK) {
            issue_b_copies(su + B_OFF + (p ^ 1u) * B_STG, z, b0 + KC, t);
            asm volatile("cp.async.commit_group;" ::: "memory");
        }

        // ---- ldmatrix + 64 HMMA per warp ----
        {
            const uint32_t Ast = su + A_OFF + p * A_STG;
            const uint32_t Bst = su + B_OFF + p * B_STG;
#pragma unroll
            for (int kk = 0; kk < 4; kk++) {
                uint32_t af[2][4];
#pragma unroll
                for (int mt = 0; mt < 2; mt++)
                    ldsm_x4(af[mt][0], af[mt][1], af[mt][2], af[mt][3],
                            Ast + (uint32_t)(rowA + mt * 16) * 128u
                                + ((((uint32_t)kk * 2u + sA) ^ rxA) << 4));
#pragma unroll
                for (int ntp = 0; ntp < 4; ntp++) {
                    uint32_t b0r, b1r, b2r, b3r;
                    ldsm_x4(b0r, b1r, b2r, b3r,
                            Bst + (uint32_t)(rowB + ntp * 16) * 128u
                               + ((((uint32_t)kk * 2u + sB) ^ rxB) << 4));
#pragma unroll
                    for (int mt = 0; mt < 2; mt++) {
                        mma16816(d[mt][2*ntp][0], d[mt][2*ntp][1], d[mt][2*ntp][2], d[mt][2*ntp][3],
                                 af[mt][0], af[mt][1], af[mt][2], af[mt][3], b0r, b1r);
                        mma16816(d[mt][2*ntp+1][0], d[mt][2*ntp+1][1], d[mt][2*ntp+1][2], d[mt][2*ntp+1][3],
                                 af[mt][0], af[mt][1], af[mt][2], af[mt][3], b2r, b3r);
                    }
                }
            }
        }
    }

    // ---- epilogue: two passes of 64 rows through smem P[64][260] ----
    float* P = reinterpret_cast<float*>(smem + A_OFF);
    const int fr = lane >> 2, fc = lane & 3;
#pragma unroll 1
    for (int half = 0; half < 2; half++) {
        __syncthreads();
        if ((m0 >> 6) == half) {
            const int mb = m0 & 63;
#pragma unroll
            for (int mt = 0; mt < 2; mt++) {
#pragma unroll
                for (int nt = 0; nt < 8; nt++) {
                    const int R0 = mb + mt * 16 + fr;
                    const int C  = n0 + nt * 8 + 2 * fc;
                    *reinterpret_cast<float2*>(P + R0 * 260 + C) =
                        make_float2(d[mt][nt][0], d[mt][nt][1]);
                    *reinterpret_cast<float2*>(P + (R0 + 8) * 260 + C) =
                        make_float2(d[mt][nt][2], d[mt][nt][3]);
                }
            }
        }
        __syncthreads();
        {
            const int al = t >> 3, iq = t & 7;         // 64 rows x 8 col-groups
            const int ar = half * 64 + al;
            const float4 ga4 = g4[a0 + ar];
            float* orow = out + ((size_t)z * NPTS + a0 + ar) * 64;
            const float* Pr = P + al * 260;
#pragma unroll
            for (int u = 0; u < 2; u++) {
                const int i0 = iq * 8 + u * 4;
                const float4 vc = *reinterpret_cast<const float4*>(Pr + i0);
                const float4 v1 = *reinterpret_cast<const float4*>(Pr + 64 + i0);
                const float4 v2 = *reinterpret_cast<const float4*>(Pr + 128 + i0);
                const float4 v3 = *reinterpret_cast<const float4*>(Pr + 192 + i0);
                float4 o;
                o.x = fmaf(-ga4.z, v3.x, fmaf(-ga4.y, v2.x, fmaf(-ga4.x, v1.x, vc.x)));
                o.y = fmaf(-ga4.z, v3.y, fmaf(-ga4.y, v2.y, fmaf(-ga4.x, v1.y, vc.y)));
                o.z = fmaf(-ga4.z, v3.z, fmaf(-ga4.y, v2.z, fmaf(-ga4.x, v1.z, vc.z)));
                o.w = fmaf(-ga4.z, v3.w, fmaf(-ga4.y, v2.w, fmaf(-ga4.x, v1.w, vc.w)));
                *reinterpret_cast<float4*>(orow + i0) = o;
            }
        }
    }
}

// ---------------------------------------------------------------------------
// Launcher. Inputs: features [8,2048,64] f32, geometry [8,2048,3] f32,
// Wk [3,64,64] f32. Output [8,2048,64] f32.
// Single compute launch; g_bar zeroed via graph-capturable memset.
// ---------------------------------------------------------------------------
extern "C" void kernel_launch(void* const* d_in, const int* in_sizes, int n_in,
                              void* d_out, int out_size) {
    const float* feat = (const float*)d_in[0];
    const float* geom = (const float*)d_in[1];
    const float* Wk   = (const float*)d_in[2];
    float* out = (float*)d_out;
    (void)in_sizes; (void)n_in; (void)out_size;

    void* bar_ptr = nullptr;
    cudaGetSymbolAddress(&bar_ptr, g_bar);
    cudaMemsetAsync(bar_ptr, 0, sizeof(int), 0);

    cudaFuncSetAttribute(conv_fused_kernel,
                         cudaFuncAttributeMaxDynamicSharedMemorySize, SMEM_MAIN);
    conv_fused_kernel<<<dim3(NPTS / MT, BATCH), THREADS, SMEM_MAIN>>>(
        feat, geom, Wk, out);
}